// round 13
// baseline (speedup 1.0000x reference)
#include <cuda_runtime.h>
#include <cmath>

#define TOKS 4096          // B_SZ * L
#define DD   1024          // D
#define NN   16            // N
#define ROWF ((2*DD + 1) * NN)   // 32784 floats per token in output
#define STRIP 8            // tokens per block

// 1/A table (no cudaMalloc allowed)
__device__ float g_R[DD * NN];

__global__ void init_R_kernel(const float* __restrict__ A)
{
    int i = blockIdx.x * blockDim.x + threadIdx.x;
    if (i < DD * NN) g_R[i] = __frcp_rn(A[i]);
}

__device__ __forceinline__ float softplus_f(float z) {
    // matches jax.nn.softplus: max(z,0) + log1p(exp(-|z|))
    return fmaxf(z, 0.f) + log1pf(__expf(-fabsf(z)));
}

__device__ __forceinline__ float dot4(float4 a, float4 b, float acc) {
    return fmaf(a.x, b.x, fmaf(a.y, b.y, fmaf(a.z, b.z, fmaf(a.w, b.w, acc))));
}

// ---------------------------------------------------------------------------
// Strip-fused kernel: block = 8 consecutive tokens.
// Phase A (bulk proj, unchanged from R10): warp = 4 W-rows x 4 tokens register
//   tile; results -> sP[33][8].
// Delta stage: sD[8][1024] = softplus for the WHOLE strip, one barrier.
// Phase B: completely barrier-free — each warp streams through all 8 tokens
//   independently (warps drift; store queue stays fed). x read via L1 (__ldg,
//   rows are L1-hot from phase A).
//   A_bar    = exp(Delta * A[d,n])
//   deltaB_x = (A_bar - 1) * R[d,n] * B[tok,n] * x[tok,d]   (Delta cancels)
// ---------------------------------------------------------------------------
__global__ __launch_bounds__(512, 2) void fused_kernel(
    const float* __restrict__ x,  const float* __restrict__ Wb,
    const float* __restrict__ Wc, const float* __restrict__ Wd,
    const float* __restrict__ A,  const float* __restrict__ dparam,
    float* __restrict__ out)
{
    __shared__ float sP[33][STRIP];    // rows 0-15: B, 16-31: C, 32: s
    __shared__ float sD[STRIP * DD];   // Delta for the whole strip (32 KB)

    const int tid  = threadIdx.x;
    const int wid  = tid >> 5;
    const int lane = tid & 31;
    const int base = blockIdx.x * STRIP;

    // ---------------- phase A: bulk projections (proven) ----------------
    {
        const int g  = wid >> 1;            // row-group 0..7
        const int th = (wid & 1) * 4;       // token-half offset 0 or 4
        const int rbase = (g < 4) ? 4 * g : 4 * (g - 4);
        const float* Wsel = (g < 4) ? Wb : Wc;
        const float4* w4  = (const float4*)(Wsel + (size_t)rbase * DD);
        const float4* xb4 = (const float4*)(x + (size_t)(base + th) * DD);
        const float4* wd4 = (const float4*)Wd;

        float acc[4][4];                    // [row][token]
        float accd[4];                      // Wd row (warps 0,1 only)
#pragma unroll
        for (int j = 0; j < 4; j++)
#pragma unroll
            for (int t = 0; t < 4; t++) acc[j][t] = 0.f;
#pragma unroll
        for (int t = 0; t < 4; t++) accd[t] = 0.f;

#pragma unroll
        for (int i = 0; i < 8; i++) {
            const int c = i * 32 + lane;    // float4 index 0..255
            float4 w0 = __ldg(w4 + 0 * 256 + c);
            float4 w1 = __ldg(w4 + 1 * 256 + c);
            float4 w2 = __ldg(w4 + 2 * 256 + c);
            float4 w3 = __ldg(w4 + 3 * 256 + c);
            float4 dv;
            if (wid < 2) dv = __ldg(wd4 + c);
#pragma unroll
            for (int t = 0; t < 4; t++) {
                float4 xv = __ldg(xb4 + t * 256 + c);
                acc[0][t] = dot4(w0, xv, acc[0][t]);
                acc[1][t] = dot4(w1, xv, acc[1][t]);
                acc[2][t] = dot4(w2, xv, acc[2][t]);
                acc[3][t] = dot4(w3, xv, acc[3][t]);
                if (wid < 2) accd[t] = dot4(dv, xv, accd[t]);
            }
        }

#pragma unroll
        for (int j = 0; j < 4; j++)
#pragma unroll
            for (int t = 0; t < 4; t++)
#pragma unroll
                for (int o = 16; o > 0; o >>= 1)
                    acc[j][t] += __shfl_xor_sync(0xffffffffu, acc[j][t], o);
        if (wid < 2)
#pragma unroll
            for (int t = 0; t < 4; t++)
#pragma unroll
                for (int o = 16; o > 0; o >>= 1)
                    accd[t] += __shfl_xor_sync(0xffffffffu, accd[t], o);

        if (lane == 0) {
            const int rowout = (g < 4) ? rbase : 16 + rbase;
#pragma unroll
            for (int j = 0; j < 4; j++)
#pragma unroll
                for (int t = 0; t < 4; t++)
                    sP[rowout + j][th + t] = acc[j][t];
            if (wid < 2)
#pragma unroll
                for (int t = 0; t < 4; t++) sP[32][th + t] = accd[t];
        }
    }
    __syncthreads();

    // ---------------- Delta stage for the whole strip ----------------
#pragma unroll
    for (int k = 0; k < STRIP * DD / 512; k++) {     // 16 elems/thread
        int i = k * 512 + tid;
        int t = i >> 10, d = i & (DD - 1);
        sD[i] = softplus_f(sP[32][t] + __ldg(dparam + d));
    }
    __syncthreads();

    // ---------------- phase B: barrier-free expansion ----------------
    const int q   = tid & 3;    // n-quad 0..3
    const int dof = tid >> 2;   // 0..127
    const float4* A4 = (const float4*)A;
    const float4* R4 = (const float4*)g_R;

#pragma unroll 1
    for (int t = 0; t < STRIP; t++) {
        const int tok = base + t;
        const float* xr = x + (size_t)tok * DD;       // L1-hot (phase A)
        const float* Dt = sD + t * DD;
        float* ob = out + (size_t)tok * ROWF;

        float4 Bq = make_float4(sP[4 * q + 0][t], sP[4 * q + 1][t],
                                sP[4 * q + 2][t], sP[4 * q + 3][t]);

        if (tid < 16)
            __stcs(ob + 2 * DD * NN + tid, sP[16 + tid][t]);

#pragma unroll
        for (int it = 0; it < 8; it++) {
            int d = dof + it * 128;
            float Delta = Dt[d];
            float xd    = __ldg(xr + d);
            float4 a = __ldg(A4 + d * 4 + q);
            float4 r = __ldg(R4 + d * 4 + q);
            float4 eo, bo;
#define COMP(f)                                                              \
            {                                                                \
                float dA = Delta * a.f;                                      \
                float e  = __expf(dA);                                       \
                float em1 = (fabsf(dA) < 0.015625f)                          \
                    ? dA * fmaf(dA, fmaf(dA, 0.16666667f, 0.5f), 1.f)        \
                    : (e - 1.f);                                             \
                eo.f = e;                                                    \
                bo.f = em1 * (r.f * (Bq.f * xd));                            \
            }
            COMP(x) COMP(y) COMP(z) COMP(w)
#undef COMP
            __stcs((float4*)ob + (size_t)d * 4 + q, eo);
            __stcs((float4*)ob + (size_t)DD * 4 + (size_t)d * 4 + q, bo);
        }
    }
}

// ---------------------------------------------------------------------------
extern "C" void kernel_launch(void* const* d_in, const int* in_sizes, int n_in,
                              void* d_out, int out_size)
{
    const float* x  = (const float*)d_in[0];
    const float* Wb = (const float*)d_in[1];
    const float* Wc = (const float*)d_in[2];
    const float* Wd = (const float*)d_in[3];
    const float* A  = (const float*)d_in[4];
    const float* dp = (const float*)d_in[5];
    float* out = (float*)d_out;

    init_R_kernel<<<32, 512>>>(A);                        // 16K rcp, ~2 us
    fused_kernel<<<TOKS / STRIP, 512>>>(x, Wb, Wc, Wd, A, dp, out);  // 512 blocks
}